// round 4
// baseline (speedup 1.0000x reference)
#include <cuda_runtime.h>
#include <cuda_bf16.h>
#include <math.h>

#define BS   32
#define BT   1024
#define DIM  512
#define NEG_MASK (-1000000.0f)
#define NEG_SPAN (-1000.0f)

// ---------------- scratch (device globals; no allocation allowed) ----------
__device__ float g_y[3][BS][DIM];     // y_w[b,d] = sum_e x[b,e] * W[e,d]
__device__ float g_c[3][BS];          // c_w[b]   = sum_e bias[e] * x[b,e]
__device__ float g_sb[BS * BT];
__device__ float g_si[BS * BT];
__device__ float g_so[BS * BT];
__device__ float g_lse[BS * BT];
__device__ float g_A[BS * BT];
__device__ float g_B[BS * BT];

// ---------------- K1: project x through the three weight matrices ---------
// grid (3, 8): blockIdx.x = weight index, blockIdx.y = batch group (4 batches)
// blockDim 512 (one thread per output dim d). W element loaded once per block,
// reused for 4 batches -> W traffic = 3MB * 8 = 24MB (L2 resident).
__global__ void proj_kernel(const float* __restrict__ x,
                            const float* __restrict__ Wb, const float* __restrict__ bb,
                            const float* __restrict__ Wi, const float* __restrict__ bi,
                            const float* __restrict__ Wo, const float* __restrict__ bo)
{
    const int w    = blockIdx.x;
    const int bgrp = blockIdx.y;            // batches bgrp*4 .. bgrp*4+3
    const float* W    = (w == 0) ? Wb : (w == 1) ? Wi : Wo;
    const float* bias = (w == 0) ? bb : (w == 1) ? bi : bo;

    __shared__ float sx[4][DIM];
    __shared__ float red[DIM];

    for (int i = threadIdx.x; i < 4 * DIM; i += blockDim.x) {
        int bb_ = i >> 9, e = i & (DIM - 1);
        sx[bb_][e] = x[(size_t)(bgrp * 4 + bb_) * DIM + e];
    }
    __syncthreads();

    const int d = threadIdx.x;
    float a0 = 0.f, a1 = 0.f, a2 = 0.f, a3 = 0.f;
#pragma unroll 4
    for (int e = 0; e < DIM; e++) {
        float wv = W[(size_t)e * DIM + d];
        a0 = fmaf(wv, sx[0][e], a0);
        a1 = fmaf(wv, sx[1][e], a1);
        a2 = fmaf(wv, sx[2][e], a2);
        a3 = fmaf(wv, sx[3][e], a3);
    }
    g_y[w][bgrp * 4 + 0][d] = a0;
    g_y[w][bgrp * 4 + 1][d] = a1;
    g_y[w][bgrp * 4 + 2][d] = a2;
    g_y[w][bgrp * 4 + 3][d] = a3;

    // c_w[b] = bias . x[b]  (block tree reduction, 4 batches)
    float bv = bias[d];
    for (int k = 0; k < 4; k++) {
        __syncthreads();
        red[d] = bv * sx[k][d];
        __syncthreads();
        for (int s = DIM / 2; s > 0; s >>= 1) {
            if (d < s) red[d] += red[d + s];
            __syncthreads();
        }
        if (d == 0) g_c[w][bgrp * 4 + k] = red[0];
    }
}

// ---------------- K2: scores + mask + logsumexp ---------------------------
// grid (BS, BT/64), blockDim 256. One warp per t-row; each row does 3
// 512-element dots against smem-resident y vectors, then fused LSE.
__global__ void scores_kernel(const float* __restrict__ sen,
                              const int*   __restrict__ mask)
{
    const int b     = blockIdx.x;
    const int tbase = blockIdx.y * 64;

    __shared__ float s_y[3][DIM];
    for (int i = threadIdx.x; i < 3 * DIM; i += blockDim.x) {
        int w = i >> 9, d = i & (DIM - 1);
        s_y[w][d] = g_y[w][b][d];
    }
    __syncthreads();

    const int warp = threadIdx.x >> 5;
    const int lane = threadIdx.x & 31;
    const float cb = g_c[0][b], ci = g_c[1][b], co = g_c[2][b];

    const float4* yb4 = (const float4*)s_y[0];
    const float4* yi4 = (const float4*)s_y[1];
    const float4* yo4 = (const float4*)s_y[2];

#pragma unroll
    for (int tt = 0; tt < 8; tt++) {
        const int t = tbase + warp * 8 + tt;
        const float4* v4 = (const float4*)(sen + ((size_t)b * BT + t) * DIM);

        float ab = 0.f, ai = 0.f, ao = 0.f;
#pragma unroll
        for (int j = 0; j < 4; j++) {
            int idx = lane + j * 32;
            float4 vv = v4[idx];
            float4 yb = yb4[idx];
            float4 yi = yi4[idx];
            float4 yo = yo4[idx];
            ab += vv.x * yb.x + vv.y * yb.y + vv.z * yb.z + vv.w * yb.w;
            ai += vv.x * yi.x + vv.y * yi.y + vv.z * yi.z + vv.w * yi.w;
            ao += vv.x * yo.x + vv.y * yo.y + vv.z * yo.z + vv.w * yo.w;
        }
#pragma unroll
        for (int off = 16; off; off >>= 1) {
            ab += __shfl_xor_sync(0xFFFFFFFFu, ab, off);
            ai += __shfl_xor_sync(0xFFFFFFFFu, ai, off);
            ao += __shfl_xor_sync(0xFFFFFFFFu, ao, off);
        }
        if (lane == 0) {
            const int   idx = b * BT + t;
            const int   m   = mask[idx];
            const float sb  = m ? (ab + cb) : NEG_MASK;
            const float si  = m ? (ai + ci) : NEG_MASK;
            const float so  = m ? (ao + co) : 0.0f;
            const float mx  = fmaxf(sb, fmaxf(si, so));
            const float lse = logf(expf(sb - mx) + expf(si - mx) + expf(so - mx)) + mx;
            g_sb[idx]  = sb;
            g_si[idx]  = si;
            g_so[idx]  = so;
            g_lse[idx] = lse;
        }
    }
}

// ---------------- K3: per-batch scans -> A, B ------------------------------
// grid BS, blockDim BT (1024). Double-precision inclusive block scan of lse
// and si, then:
//   A[t] = sb[t] + fwd_excl[t] - Ci_excl[t] - full
//   B[t] = Ci_excl[t] + (full - incl_lse[t]) + so[t]
__global__ void scan_kernel()
{
    const int b   = blockIdx.x;
    const int t   = threadIdx.x;
    const int idx = b * BT + t;
    const int lane = t & 31, wid = t >> 5;

    const float lse_f = g_lse[idx];
    const float si_f  = g_si[idx];
    double vl = (double)lse_f;
    double vs = (double)si_f;

    // intra-warp inclusive scan
#pragma unroll
    for (int o = 1; o < 32; o <<= 1) {
        double nl = __shfl_up_sync(0xFFFFFFFFu, vl, o);
        double ns = __shfl_up_sync(0xFFFFFFFFu, vs, o);
        if (lane >= o) { vl += nl; vs += ns; }
    }

    __shared__ double wl[32], ws[32];
    if (lane == 31) { wl[wid] = vl; ws[wid] = vs; }
    __syncthreads();
    if (wid == 0) {
        double a = wl[lane], c = ws[lane];
#pragma unroll
        for (int o = 1; o < 32; o <<= 1) {
            double na = __shfl_up_sync(0xFFFFFFFFu, a, o);
            double nc = __shfl_up_sync(0xFFFFFFFFu, c, o);
            if (lane >= o) { a += na; c += nc; }
        }
        wl[lane] = a; ws[lane] = c;
    }
    __syncthreads();

    const double off_l = wid ? wl[wid - 1] : 0.0;
    const double off_s = wid ? ws[wid - 1] : 0.0;
    const double incl_l = vl + off_l;
    const double incl_s = vs + off_s;
    const double full   = wl[31];

    const double fwd_ex = incl_l - (double)lse_f;   // sum lse[0..t-1]
    const double Ci_ex  = incl_s - (double)si_f;    // sum si[0..t-1]

    g_A[idx] = g_sb[idx] + (float)(fwd_ex - Ci_ex - full);
    g_B[idx] = (float)(Ci_ex + (full - incl_l)) + g_so[idx];
}

// ---------------- K4: span fill (write-bound) ------------------------------
// grid (BT/16, BS), blockDim 256. Each block covers 16 consecutive i-rows
// across the full j dimension; B row held in smem; float4 coalesced stores.
__global__ void span_kernel(float* __restrict__ out)
{
    const int b  = blockIdx.y;
    const int i0 = blockIdx.x * 16;

    __shared__ float sB[BT];
    __shared__ float sA[16];

    for (int j = threadIdx.x; j < BT; j += 256) sB[j] = g_B[b * BT + j];
    if (threadIdx.x < 16) sA[threadIdx.x] = g_A[b * BT + i0 + threadIdx.x];
    __syncthreads();

    const int j = threadIdx.x * 4;
    const float b0 = sB[j], b1 = sB[j + 1], b2 = sB[j + 2], b3 = sB[j + 3];

    float4* op = (float4*)(out + ((size_t)b * BT + i0) * BT) + threadIdx.x;
#pragma unroll
    for (int r = 0; r < 16; r++) {
        const int   i = i0 + r;
        const float a = sA[r];
        float4 v;
        v.x = (j     >= i) ? (a + b0) : NEG_SPAN;
        v.y = (j + 1 >= i) ? (a + b1) : NEG_SPAN;
        v.z = (j + 2 >= i) ? (a + b2) : NEG_SPAN;
        v.w = (j + 3 >= i) ? (a + b3) : NEG_SPAN;
        op[(size_t)r * (BT / 4)] = v;
    }
}

// ---------------- launch ---------------------------------------------------
extern "C" void kernel_launch(void* const* d_in, const int* in_sizes, int n_in,
                              void* d_out, int out_size)
{
    const float* x   = (const float*)d_in[0];
    const float* sen = (const float*)d_in[1];
    const int*   msk = (const int*)  d_in[2];
    const float* Wb  = (const float*)d_in[3];
    const float* bb  = (const float*)d_in[4];
    const float* Wi  = (const float*)d_in[5];
    const float* bi  = (const float*)d_in[6];
    const float* Wo  = (const float*)d_in[7];
    const float* bo  = (const float*)d_in[8];
    float* out = (float*)d_out;

    proj_kernel  <<<dim3(3, 8),        512>>>(x, Wb, bb, Wi, bi, Wo, bo);
    scores_kernel<<<dim3(BS, BT / 64), 256>>>(sen, msk);
    scan_kernel  <<<BS,                BT >>>();
    span_kernel  <<<dim3(BT / 16, BS), 256>>>(out);
}

// round 5
// speedup vs baseline: 1.6672x; 1.6672x over previous
#include <cuda_runtime.h>
#include <cuda_bf16.h>
#include <math.h>

#define BS   32
#define BT   1024
#define DIM  512
#define NCH  8
#define CHUNK (DIM / NCH)          // 64
#define NEG_MASK (-1000000.0f)
#define NEG_SPAN (-1000.0f)

// ---------------- scratch (device globals; no allocation allowed) ----------
__device__ float g_yp[NCH][3][BS][DIM];   // split-K partials
__device__ float g_y[3][BS][DIM];         // y_w[b,d] = sum_e x[b,e] * W[e,d]
__device__ float g_c[3][BS];              // c_w[b]   = bias_w . x[b]
__device__ float g_sb[BS * BT];
__device__ float g_si[BS * BT];
__device__ float g_so[BS * BT];
__device__ float g_lse[BS * BT];
__device__ float g_A[BS * BT];
__device__ float g_B[BS * BT];

// ---------------- K1: split-K projection -----------------------------------
// grid (3, BS, NCH) = 768 blocks, block 512 (one thread per output dim d).
// Each block contracts a 64-row e-chunk of W against x[b]. W (3MB) is fully
// L2-resident across the 32-batch reuse.
__global__ void proj_chunk_kernel(const float* __restrict__ x,
                                  const float* __restrict__ Wb,
                                  const float* __restrict__ Wi,
                                  const float* __restrict__ Wo)
{
    const int w  = blockIdx.x;
    const int b  = blockIdx.y;
    const int ch = blockIdx.z;
    const float* W = (w == 0) ? Wb : (w == 1) ? Wi : Wo;

    __shared__ float sx[CHUNK];
    if (threadIdx.x < CHUNK)
        sx[threadIdx.x] = x[(size_t)b * DIM + ch * CHUNK + threadIdx.x];
    __syncthreads();

    const int d = threadIdx.x;
    const float* Wp = W + (size_t)(ch * CHUNK) * DIM + d;
    float acc = 0.f;
#pragma unroll 8
    for (int e = 0; e < CHUNK; e++)
        acc = fmaf(Wp[(size_t)e * DIM], sx[e], acc);
    g_yp[ch][w][b][d] = acc;
}

// ---------------- K1b: reduce partials + bias dots -------------------------
// grid (3, BS) = 96 blocks, block 512.
__global__ void reduce_kernel(const float* __restrict__ x,
                              const float* __restrict__ bb,
                              const float* __restrict__ bi,
                              const float* __restrict__ bo)
{
    const int w = blockIdx.x;
    const int b = blockIdx.y;
    const float* bias = (w == 0) ? bb : (w == 1) ? bi : bo;

    const int d = threadIdx.x;
    float s = 0.f;
#pragma unroll
    for (int ch = 0; ch < NCH; ch++) s += g_yp[ch][w][b][d];
    g_y[w][b][d] = s;

    // bias . x[b] with warp shuffles + one smem hop
    float p = bias[d] * x[(size_t)b * DIM + d];
#pragma unroll
    for (int off = 16; off; off >>= 1)
        p += __shfl_xor_sync(0xFFFFFFFFu, p, off);

    __shared__ float red[16];
    const int lane = d & 31, wid = d >> 5;
    if (lane == 0) red[wid] = p;
    __syncthreads();
    if (wid == 0) {
        float q = (lane < 16) ? red[lane] : 0.f;
#pragma unroll
        for (int off = 8; off; off >>= 1)
            q += __shfl_xor_sync(0xFFFFFFFFu, q, off);
        if (lane == 0) g_c[w][b] = q;
    }
}

// ---------------- K2: scores + mask + logsumexp ---------------------------
// grid (BS, BT/64), blockDim 256. One warp per t-row; three 512-dots against
// smem-resident y, then fused LSE. Bound by the 64MB sen_vecs read.
__global__ void scores_kernel(const float* __restrict__ sen,
                              const int*   __restrict__ mask)
{
    const int b     = blockIdx.x;
    const int tbase = blockIdx.y * 64;

    __shared__ float s_y[3][DIM];
    for (int i = threadIdx.x; i < 3 * DIM; i += blockDim.x) {
        int w = i >> 9, d = i & (DIM - 1);
        s_y[w][d] = g_y[w][b][d];
    }
    __syncthreads();

    const int warp = threadIdx.x >> 5;
    const int lane = threadIdx.x & 31;
    const float cb = g_c[0][b], ci = g_c[1][b], co = g_c[2][b];

    const float4* yb4 = (const float4*)s_y[0];
    const float4* yi4 = (const float4*)s_y[1];
    const float4* yo4 = (const float4*)s_y[2];

#pragma unroll
    for (int tt = 0; tt < 8; tt++) {
        const int t = tbase + warp * 8 + tt;
        const float4* v4 = (const float4*)(sen + ((size_t)b * BT + t) * DIM);

        float ab = 0.f, ai = 0.f, ao = 0.f;
#pragma unroll
        for (int j = 0; j < 4; j++) {
            int idx = lane + j * 32;
            float4 vv = v4[idx];
            float4 yb = yb4[idx];
            float4 yi = yi4[idx];
            float4 yo = yo4[idx];
            ab += vv.x * yb.x + vv.y * yb.y + vv.z * yb.z + vv.w * yb.w;
            ai += vv.x * yi.x + vv.y * yi.y + vv.z * yi.z + vv.w * yi.w;
            ao += vv.x * yo.x + vv.y * yo.y + vv.z * yo.z + vv.w * yo.w;
        }
#pragma unroll
        for (int off = 16; off; off >>= 1) {
            ab += __shfl_xor_sync(0xFFFFFFFFu, ab, off);
            ai += __shfl_xor_sync(0xFFFFFFFFu, ai, off);
            ao += __shfl_xor_sync(0xFFFFFFFFu, ao, off);
        }
        if (lane == 0) {
            const int   idx = b * BT + t;
            const int   m   = mask[idx];
            const float sb  = m ? (ab + cb) : NEG_MASK;
            const float si  = m ? (ai + ci) : NEG_MASK;
            const float so  = m ? (ao + co) : 0.0f;
            const float mx  = fmaxf(sb, fmaxf(si, so));
            const float lse = logf(expf(sb - mx) + expf(si - mx) + expf(so - mx)) + mx;
            g_sb[idx]  = sb;
            g_si[idx]  = si;
            g_so[idx]  = so;
            g_lse[idx] = lse;
        }
    }
}

// ---------------- K3: per-batch scans -> A, B ------------------------------
__global__ void scan_kernel()
{
    const int b   = blockIdx.x;
    const int t   = threadIdx.x;
    const int idx = b * BT + t;
    const int lane = t & 31, wid = t >> 5;

    const float lse_f = g_lse[idx];
    const float si_f  = g_si[idx];
    double vl = (double)lse_f;
    double vs = (double)si_f;

#pragma unroll
    for (int o = 1; o < 32; o <<= 1) {
        double nl = __shfl_up_sync(0xFFFFFFFFu, vl, o);
        double ns = __shfl_up_sync(0xFFFFFFFFu, vs, o);
        if (lane >= o) { vl += nl; vs += ns; }
    }

    __shared__ double wl[32], ws[32];
    if (lane == 31) { wl[wid] = vl; ws[wid] = vs; }
    __syncthreads();
    if (wid == 0) {
        double a = wl[lane], c = ws[lane];
#pragma unroll
        for (int o = 1; o < 32; o <<= 1) {
            double na = __shfl_up_sync(0xFFFFFFFFu, a, o);
            double nc = __shfl_up_sync(0xFFFFFFFFu, c, o);
            if (lane >= o) { a += na; c += nc; }
        }
        wl[lane] = a; ws[lane] = c;
    }
    __syncthreads();

    const double off_l = wid ? wl[wid - 1] : 0.0;
    const double off_s = wid ? ws[wid - 1] : 0.0;
    const double incl_l = vl + off_l;
    const double incl_s = vs + off_s;
    const double full   = wl[31];

    const double fwd_ex = incl_l - (double)lse_f;
    const double Ci_ex  = incl_s - (double)si_f;

    g_A[idx] = g_sb[idx] + (float)(fwd_ex - Ci_ex - full);
    g_B[idx] = (float)(Ci_ex + (full - incl_l)) + g_so[idx];
}

// ---------------- K4: span fill (write-bound) ------------------------------
// grid (BT/16, BS), blockDim 256. Streaming (evict-first) float4 stores.
__global__ void span_kernel(float* __restrict__ out)
{
    const int b  = blockIdx.y;
    const int i0 = blockIdx.x * 16;

    __shared__ float sB[BT];
    __shared__ float sA[16];

    for (int j = threadIdx.x; j < BT; j += 256) sB[j] = g_B[b * BT + j];
    if (threadIdx.x < 16) sA[threadIdx.x] = g_A[b * BT + i0 + threadIdx.x];
    __syncthreads();

    const int j = threadIdx.x * 4;
    const float b0 = sB[j], b1 = sB[j + 1], b2 = sB[j + 2], b3 = sB[j + 3];

    float4* op = (float4*)(out + ((size_t)b * BT + i0) * BT) + threadIdx.x;
#pragma unroll
    for (int r = 0; r < 16; r++) {
        const int   i = i0 + r;
        const float a = sA[r];
        float4 v;
        v.x = (j     >= i) ? (a + b0) : NEG_SPAN;
        v.y = (j + 1 >= i) ? (a + b1) : NEG_SPAN;
        v.z = (j + 2 >= i) ? (a + b2) : NEG_SPAN;
        v.w = (j + 3 >= i) ? (a + b3) : NEG_SPAN;
        __stcs(op + (size_t)r * (BT / 4), v);
    }
}

// ---------------- launch ---------------------------------------------------
extern "C" void kernel_launch(void* const* d_in, const int* in_sizes, int n_in,
                              void* d_out, int out_size)
{
    const float* x   = (const float*)d_in[0];
    const float* sen = (const float*)d_in[1];
    const int*   msk = (const int*)  d_in[2];
    const float* Wb  = (const float*)d_in[3];
    const float* bb  = (const float*)d_in[4];
    const float* Wi  = (const float*)d_in[5];
    const float* bi  = (const float*)d_in[6];
    const float* Wo  = (const float*)d_in[7];
    const float* bo  = (const float*)d_in[8];
    float* out = (float*)d_out;

    proj_chunk_kernel<<<dim3(3, BS, NCH), 512>>>(x, Wb, Wi, Wo);
    reduce_kernel    <<<dim3(3, BS),      512>>>(x, bb, bi, bo);
    scores_kernel    <<<dim3(BS, BT / 64), 256>>>(sen, msk);
    scan_kernel      <<<BS,               BT >>>();
    span_kernel      <<<dim3(BT / 16, BS), 256>>>(out);
}

// round 8
// speedup vs baseline: 1.6834x; 1.0097x over previous
#include <cuda_runtime.h>
#include <cuda_bf16.h>
#include <math.h>

#define BS   32
#define BT   1024
#define DIM  512
#define NCH  8
#define CHUNK (DIM / NCH)          // 64
#define NEG_MASK (-1000000.0f)
#define NEG_SPAN (-1000.0f)

// ---------------- scratch (device globals; no allocation allowed) ----------
__device__ __align__(16) float g_yp[NCH][3][BS][DIM];   // split-K partials
__device__ __align__(16) float g_sb[BS * BT];
__device__ __align__(16) float g_si[BS * BT];
__device__ __align__(16) float g_so[BS * BT];
__device__ __align__(16) float g_lse[BS * BT];
__device__ __align__(16) float g_A[BS * BT];
__device__ __align__(16) float g_B[BS * BT];

// ---------------- K1: split-K projection with 4-batch W reuse --------------
// grid (3, 8, 8): w, batch-group (4 batches), e-chunk. block 512 (thread=d).
// W traffic: 192 blocks * 128KB = 24MB L2 (W itself 3MB -> DRAM once).
__global__ void proj_kernel(const float* __restrict__ x,
                            const float* __restrict__ Wb,
                            const float* __restrict__ Wi,
                            const float* __restrict__ Wo)
{
    const int w    = blockIdx.x;
    const int bgrp = blockIdx.y;
    const int ch   = blockIdx.z;
    const float* W = (w == 0) ? Wb : (w == 1) ? Wi : Wo;

    __shared__ float sx[4][CHUNK];
    if (threadIdx.x < 4 * CHUNK) {
        int k = threadIdx.x >> 6, e = threadIdx.x & (CHUNK - 1);
        sx[k][e] = x[(size_t)(bgrp * 4 + k) * DIM + ch * CHUNK + e];
    }
    __syncthreads();

    const int d = threadIdx.x;
    const float* Wp = W + (size_t)(ch * CHUNK) * DIM + d;
    float a0 = 0.f, a1 = 0.f, a2 = 0.f, a3 = 0.f;
#pragma unroll 8
    for (int e = 0; e < CHUNK; e++) {
        float wv = Wp[(size_t)e * DIM];
        a0 = fmaf(wv, sx[0][e], a0);
        a1 = fmaf(wv, sx[1][e], a1);
        a2 = fmaf(wv, sx[2][e], a2);
        a3 = fmaf(wv, sx[3][e], a3);
    }
    g_yp[ch][w][bgrp * 4 + 0][d] = a0;
    g_yp[ch][w][bgrp * 4 + 1][d] = a1;
    g_yp[ch][w][bgrp * 4 + 2][d] = a2;
    g_yp[ch][w][bgrp * 4 + 3][d] = a3;
}

// ---------------- K2: fused reduce + scores + mask + logsumexp -------------
// grid (BS, BT/64), block 256 (8 warps x 8 rows). Prologue folds the split-K
// partials into smem y and computes the three bias dots. One warp per t-row,
// three 512-dots, fused LSE. Bound by the 64MB sen read.
__global__ void scores_kernel(const float* __restrict__ sen,
                              const int*   __restrict__ mask,
                              const float* __restrict__ x,
                              const float* __restrict__ bb,
                              const float* __restrict__ bi,
                              const float* __restrict__ bo)
{
    const int b     = blockIdx.x;
    const int tbase = blockIdx.y * 64;
    const int warp  = threadIdx.x >> 5;
    const int lane  = threadIdx.x & 31;

    __shared__ float s_y[3][DIM];
    __shared__ float s_c[3];

    // fold split-K partials: each thread produces 6 of the 1536 y values
    for (int i = threadIdx.x; i < 3 * DIM; i += 256) {
        int w = i >> 9, d = i & (DIM - 1);
        float s = 0.f;
#pragma unroll
        for (int ch = 0; ch < NCH; ch++) s += g_yp[ch][w][b][d];
        s_y[w][d] = s;
    }
    // bias dots: warps 0..2 compute c_w = bias_w . x[b]
    if (warp < 3) {
        const float* bias = (warp == 0) ? bb : (warp == 1) ? bi : bo;
        float p = 0.f;
#pragma unroll
        for (int k = lane; k < DIM; k += 32)
            p = fmaf(bias[k], x[(size_t)b * DIM + k], p);
#pragma unroll
        for (int off = 16; off; off >>= 1)
            p += __shfl_xor_sync(0xFFFFFFFFu, p, off);
        if (lane == 0) s_c[warp] = p;
    }
    __syncthreads();

    const float cb = s_c[0], ci = s_c[1], co = s_c[2];
    const float4* yb4 = (const float4*)s_y[0];
    const float4* yi4 = (const float4*)s_y[1];
    const float4* yo4 = (const float4*)s_y[2];

#pragma unroll
    for (int tt = 0; tt < 8; tt++) {
        const int t = tbase + warp * 8 + tt;
        const float4* v4 = (const float4*)(sen + ((size_t)b * BT + t) * DIM);

        float ab = 0.f, ai = 0.f, ao = 0.f;
#pragma unroll
        for (int j = 0; j < 4; j++) {
            int idx = lane + j * 32;
            float4 vv = v4[idx];
            float4 yb = yb4[idx];
            float4 yi = yi4[idx];
            float4 yo = yo4[idx];
            ab += vv.x * yb.x + vv.y * yb.y + vv.z * yb.z + vv.w * yb.w;
            ai += vv.x * yi.x + vv.y * yi.y + vv.z * yi.z + vv.w * yi.w;
            ao += vv.x * yo.x + vv.y * yo.y + vv.z * yo.z + vv.w * yo.w;
        }
#pragma unroll
        for (int off = 16; off; off >>= 1) {
            ab += __shfl_xor_sync(0xFFFFFFFFu, ab, off);
            ai += __shfl_xor_sync(0xFFFFFFFFu, ai, off);
            ao += __shfl_xor_sync(0xFFFFFFFFu, ao, off);
        }
        if (lane == 0) {
            const int   idx = b * BT + t;
            const int   m   = mask[idx];
            const float sb  = m ? (ab + cb) : NEG_MASK;
            const float si  = m ? (ai + ci) : NEG_MASK;
            const float so  = m ? (ao + co) : 0.0f;
            const float mx  = fmaxf(sb, fmaxf(si, so));
            const float lse = logf(expf(sb - mx) + expf(si - mx) + expf(so - mx)) + mx;
            g_sb[idx]  = sb;
            g_si[idx]  = si;
            g_so[idx]  = so;
            g_lse[idx] = lse;
        }
    }
}

// ---------------- K3: per-batch scans -> A, B (chunked, short chain) -------
// grid BS, block 256. Thread owns 4 contiguous elements: 3 serial DADDs,
// one 5-level warp scan, 8-value smem combine.
__global__ void scan_kernel()
{
    const int b    = blockIdx.x;
    const int tid  = threadIdx.x;
    const int lane = tid & 31, wid = tid >> 5;
    const int idx0 = b * BT + tid * 4;

    const float4 l4 = *(const float4*)(g_lse + idx0);
    const float4 s4 = *(const float4*)(g_si  + idx0);

    // inclusive prefix inside the 4-chunk (double)
    const double lp0 = (double)l4.x;
    const double lp1 = lp0 + (double)l4.y;
    const double lp2 = lp1 + (double)l4.z;
    const double lp3 = lp2 + (double)l4.w;
    const double sp0 = (double)s4.x;
    const double sp1 = sp0 + (double)s4.y;
    const double sp2 = sp1 + (double)s4.z;
    const double sp3 = sp2 + (double)s4.w;

    // inclusive warp scan of chunk totals
    double tl = lp3, ts = sp3;
#pragma unroll
    for (int o = 1; o < 32; o <<= 1) {
        double nl = __shfl_up_sync(0xFFFFFFFFu, tl, o);
        double ns = __shfl_up_sync(0xFFFFFFFFu, ts, o);
        if (lane >= o) { tl += nl; ts += ns; }
    }

    __shared__ double swl[8], sws[8];
    if (lane == 31) { swl[wid] = tl; sws[wid] = ts; }
    __syncthreads();

    double base_l = 0.0, base_s = 0.0, full_l = 0.0;
#pragma unroll
    for (int w = 0; w < 8; w++) {
        double a = swl[w], c = sws[w];
        full_l += a;
        if (w < wid) { base_l += a; base_s += c; }
    }

    // exclusive prefix before this thread's chunk
    const double ex_l = base_l + (tl - lp3);
    const double ex_s = base_s + (ts - sp3);

    const float4 b4 = *(const float4*)(g_sb + idx0);
    const float4 o4 = *(const float4*)(g_so + idx0);

    // A[t] = sb + fwd_ex - Ci_ex - full ;  B[t] = Ci_ex + (full - incl_lse) + so
    float4 A, Bv;
    A.x  = b4.x + (float)( ex_l         - ex_s          - full_l);
    Bv.x = (float)( ex_s         + (full_l - (ex_l + lp0))) + o4.x;
    A.y  = b4.y + (float)((ex_l + lp0) - (ex_s + sp0)  - full_l);
    Bv.y = (float)((ex_s + sp0) + (full_l - (ex_l + lp1))) + o4.y;
    A.z  = b4.z + (float)((ex_l + lp1) - (ex_s + sp1)  - full_l);
    Bv.z = (float)((ex_s + sp1) + (full_l - (ex_l + lp2))) + o4.z;
    A.w  = b4.w + (float)((ex_l + lp2) - (ex_s + sp2)  - full_l);
    Bv.w = (float)((ex_s + sp2) + (full_l - (ex_l + lp3))) + o4.w;

    *(float4*)(g_A + idx0) = A;
    *(float4*)(g_B + idx0) = Bv;
}

// ---------------- K4: span fill (write-bound) ------------------------------
// grid (BT/16, BS), block 256. Streaming (evict-first) float4 stores.
__global__ void span_kernel(float* __restrict__ out)
{
    const int b  = blockIdx.y;
    const int i0 = blockIdx.x * 16;

    __shared__ float sB[BT];
    __shared__ float sA[16];

    for (int j = threadIdx.x; j < BT; j += 256) sB[j] = g_B[b * BT + j];
    if (threadIdx.x < 16) sA[threadIdx.x] = g_A[b * BT + i0 + threadIdx.x];
    __syncthreads();

    const int j = threadIdx.x * 4;
    const float b0 = sB[j], b1 = sB[j + 1], b2 = sB[j + 2], b3 = sB[j + 3];

    float4* op = (float4*)(out + ((size_t)b * BT + i0) * BT) + threadIdx.x;
#pragma unroll
    for (int r = 0; r < 16; r++) {
        const int   i = i0 + r;
        const float a = sA[r];
        float4 v;
        v.x = (j     >= i) ? (a + b0) : NEG_SPAN;
        v.y = (j + 1 >= i) ? (a + b1) : NEG_SPAN;
        v.z = (j + 2 >= i) ? (a + b2) : NEG_SPAN;
        v.w = (j + 3 >= i) ? (a + b3) : NEG_SPAN;
        __stcs(op + (size_t)r * (BT / 4), v);
    }
}

// ---------------- launch ---------------------------------------------------
extern "C" void kernel_launch(void* const* d_in, const int* in_sizes, int n_in,
                              void* d_out, int out_size)
{
    const float* x   = (const float*)d_in[0];
    const float* sen = (const float*)d_in[1];
    const int*   msk = (const int*)  d_in[2];
    const float* Wb  = (const float*)d_in[3];
    const float* bb  = (const float*)d_in[4];
    const float* Wi  = (const float*)d_in[5];
    const float* bi  = (const float*)d_in[6];
    const float* Wo  = (const float*)d_in[7];
    const float* bo  = (const float*)d_in[8];
    float* out = (float*)d_out;

    proj_kernel  <<<dim3(3, 8, NCH),    512>>>(x, Wb, Wi, Wo);
    scores_kernel<<<dim3(BS, BT / 64),  256>>>(sen, msk, x, bb, bi, bo);
    scan_kernel  <<<BS,                 256>>>();
    span_kernel  <<<dim3(BT / 16, BS),  256>>>(out);
}

// round 12
// speedup vs baseline: 1.7765x; 1.0553x over previous
#include <cuda_runtime.h>
#include <cuda_bf16.h>
#include <math.h>

#define BS   32
#define BT   1024
#define DIM  512
#define NCH  8
#define CHUNK (DIM / NCH)          // 64
#define NEG_MASK (-1000000.0f)
#define NEG_SPAN (-1000.0f)

// ---------------- scratch (device globals; no allocation allowed) ----------
__device__ __align__(16) float g_yp[NCH][3][BS][DIM];   // split-K partials
__device__ __align__(16) float g_sb[BS * BT];
__device__ __align__(16) float g_si[BS * BT];
__device__ __align__(16) float g_so[BS * BT];
__device__ __align__(16) float g_lse[BS * BT];
__device__ __align__(16) float g_A[BS * BT];
__device__ __align__(16) float g_B[BS * BT];

// ---------------- K1: split-K projection, float4 W loads -------------------
// grid (3, 8, 8): w, batch-group (4 batches), e-chunk. block 128, thread owns
// 4 consecutive d-columns (one float4 per e). W L2 traffic 24MB, DRAM 3MB.
__global__ void __launch_bounds__(128)
proj_kernel(const float* __restrict__ x,
            const float* __restrict__ Wb,
            const float* __restrict__ Wi,
            const float* __restrict__ Wo)
{
    const int w    = blockIdx.x;
    const int bgrp = blockIdx.y;
    const int ch   = blockIdx.z;
    const float* W = (w == 0) ? Wb : (w == 1) ? Wi : Wo;

    __shared__ float sx[4][CHUNK];
    for (int i = threadIdx.x; i < 4 * CHUNK; i += 128) {
        int k = i >> 6, e = i & (CHUNK - 1);
        sx[k][e] = x[(size_t)(bgrp * 4 + k) * DIM + ch * CHUNK + e];
    }
    __syncthreads();

    const float4* Wp = (const float4*)(W + (size_t)(ch * CHUNK) * DIM) + threadIdx.x;
    float4 a0 = {0,0,0,0}, a1 = {0,0,0,0}, a2 = {0,0,0,0}, a3 = {0,0,0,0};
#pragma unroll 4
    for (int e = 0; e < CHUNK; e++) {
        const float4 wv = Wp[(size_t)e * (DIM / 4)];
        const float x0 = sx[0][e], x1 = sx[1][e], x2 = sx[2][e], x3 = sx[3][e];
        a0.x = fmaf(wv.x, x0, a0.x); a0.y = fmaf(wv.y, x0, a0.y);
        a0.z = fmaf(wv.z, x0, a0.z); a0.w = fmaf(wv.w, x0, a0.w);
        a1.x = fmaf(wv.x, x1, a1.x); a1.y = fmaf(wv.y, x1, a1.y);
        a1.z = fmaf(wv.z, x1, a1.z); a1.w = fmaf(wv.w, x1, a1.w);
        a2.x = fmaf(wv.x, x2, a2.x); a2.y = fmaf(wv.y, x2, a2.y);
        a2.z = fmaf(wv.z, x2, a2.z); a2.w = fmaf(wv.w, x2, a2.w);
        a3.x = fmaf(wv.x, x3, a3.x); a3.y = fmaf(wv.y, x3, a3.y);
        a3.z = fmaf(wv.z, x3, a3.z); a3.w = fmaf(wv.w, x3, a3.w);
    }
    ((float4*)g_yp[ch][w][bgrp * 4 + 0])[threadIdx.x] = a0;
    ((float4*)g_yp[ch][w][bgrp * 4 + 1])[threadIdx.x] = a1;
    ((float4*)g_yp[ch][w][bgrp * 4 + 2])[threadIdx.x] = a2;
    ((float4*)g_yp[ch][w][bgrp * 4 + 3])[threadIdx.x] = a3;
}

// ---------------- K2: fused reduce + scores + mask + logsumexp -------------
// grid (BS, 16), block 256 (8 warps x 8 rows). Prologue folds split-K
// partials into smem, then each lane hoists its y-slices into REGISTERS
// (12 float4 = 48 regs) so the row loop has zero LDS traffic.
__global__ void __launch_bounds__(256)
scores_kernel(const float* __restrict__ sen,
              const int*   __restrict__ mask,
              const float* __restrict__ x,
              const float* __restrict__ bb,
              const float* __restrict__ bi,
              const float* __restrict__ bo)
{
    const int b     = blockIdx.x;
    const int tbase = blockIdx.y * 64;
    const int warp  = threadIdx.x >> 5;
    const int lane  = threadIdx.x & 31;

    __shared__ float s_y[3][DIM];
    __shared__ float s_c[3];

    // fold split-K partials
    for (int i = threadIdx.x; i < 3 * DIM; i += 256) {
        int w = i >> 9, d = i & (DIM - 1);
        float s = 0.f;
#pragma unroll
        for (int ch = 0; ch < NCH; ch++) s += g_yp[ch][w][b][d];
        s_y[w][d] = s;
    }
    // bias dots: warps 0..2 compute c_w = bias_w . x[b]
    if (warp < 3) {
        const float* bias = (warp == 0) ? bb : (warp == 1) ? bi : bo;
        float p = 0.f;
#pragma unroll
        for (int k = lane; k < DIM; k += 32)
            p = fmaf(bias[k], x[(size_t)b * DIM + k], p);
#pragma unroll
        for (int off = 16; off; off >>= 1)
            p += __shfl_xor_sync(0xFFFFFFFFu, p, off);
        if (lane == 0) s_c[warp] = p;
    }
    __syncthreads();

    // hoist y slices into registers
    float4 ryb[4], ryi[4], ryo[4];
    {
        const float4* yb4 = (const float4*)s_y[0];
        const float4* yi4 = (const float4*)s_y[1];
        const float4* yo4 = (const float4*)s_y[2];
#pragma unroll
        for (int j = 0; j < 4; j++) {
            ryb[j] = yb4[lane + j * 32];
            ryi[j] = yi4[lane + j * 32];
            ryo[j] = yo4[lane + j * 32];
        }
    }
    const float cb = s_c[0], ci = s_c[1], co = s_c[2];

#pragma unroll
    for (int tt = 0; tt < 8; tt++) {
        const int t = tbase + warp * 8 + tt;
        const float4* v4 = (const float4*)(sen + ((size_t)b * BT + t) * DIM);

        float ab = 0.f, ai = 0.f, ao = 0.f;
#pragma unroll
        for (int j = 0; j < 4; j++) {
            const float4 vv = v4[lane + j * 32];
            ab = fmaf(vv.x, ryb[j].x, ab); ab = fmaf(vv.y, ryb[j].y, ab);
            ab = fmaf(vv.z, ryb[j].z, ab); ab = fmaf(vv.w, ryb[j].w, ab);
            ai = fmaf(vv.x, ryi[j].x, ai); ai = fmaf(vv.y, ryi[j].y, ai);
            ai = fmaf(vv.z, ryi[j].z, ai); ai = fmaf(vv.w, ryi[j].w, ai);
            ao = fmaf(vv.x, ryo[j].x, ao); ao = fmaf(vv.y, ryo[j].y, ao);
            ao = fmaf(vv.z, ryo[j].z, ao); ao = fmaf(vv.w, ryo[j].w, ao);
        }
#pragma unroll
        for (int off = 16; off; off >>= 1) {
            ab += __shfl_xor_sync(0xFFFFFFFFu, ab, off);
            ai += __shfl_xor_sync(0xFFFFFFFFu, ai, off);
            ao += __shfl_xor_sync(0xFFFFFFFFu, ao, off);
        }
        if (lane == 0) {
            const int   idx = b * BT + t;
            const int   m   = mask[idx];
            const float sb  = m ? (ab + cb) : NEG_MASK;
            const float si  = m ? (ai + ci) : NEG_MASK;
            const float so  = m ? (ao + co) : 0.0f;
            const float mx  = fmaxf(sb, fmaxf(si, so));
            const float lse = logf(expf(sb - mx) + expf(si - mx) + expf(so - mx)) + mx;
            g_sb[idx]  = sb;
            g_si[idx]  = si;
            g_so[idx]  = so;
            g_lse[idx] = lse;
        }
    }
}

// ---------------- K3: per-batch scans -> A, B (chunked, short chain) -------
__global__ void __launch_bounds__(256) scan_kernel()
{
    const int b    = blockIdx.x;
    const int tid  = threadIdx.x;
    const int lane = tid & 31, wid = tid >> 5;
    const int idx0 = b * BT + tid * 4;

    const float4 l4 = *(const float4*)(g_lse + idx0);
    const float4 s4 = *(const float4*)(g_si  + idx0);

    const double lp0 = (double)l4.x;
    const double lp1 = lp0 + (double)l4.y;
    const double lp2 = lp1 + (double)l4.z;
    const double lp3 = lp2 + (double)l4.w;
    const double sp0 = (double)s4.x;
    const double sp1 = sp0 + (double)s4.y;
    const double sp2 = sp1 + (double)s4.z;
    const double sp3 = sp2 + (double)s4.w;

    double tl = lp3, ts = sp3;
#pragma unroll
    for (int o = 1; o < 32; o <<= 1) {
        double nl = __shfl_up_sync(0xFFFFFFFFu, tl, o);
        double ns = __shfl_up_sync(0xFFFFFFFFu, ts, o);
        if (lane >= o) { tl += nl; ts += ns; }
    }

    __shared__ double swl[8], sws[8];
    if (lane == 31) { swl[wid] = tl; sws[wid] = ts; }
    __syncthreads();

    double base_l = 0.0, base_s = 0.0, full_l = 0.0;
#pragma unroll
    for (int w = 0; w < 8; w++) {
        double a = swl[w], c = sws[w];
        full_l += a;
        if (w < wid) { base_l += a; base_s += c; }
    }

    const double ex_l = base_l + (tl - lp3);
    const double ex_s = base_s + (ts - sp3);

    const float4 b4 = *(const float4*)(g_sb + idx0);
    const float4 o4 = *(const float4*)(g_so + idx0);

    float4 A, Bv;
    A.x  = b4.x + (float)( ex_l         - ex_s          - full_l);
    Bv.x = (float)( ex_s         + (full_l - (ex_l + lp0))) + o4.x;
    A.y  = b4.y + (float)((ex_l + lp0) - (ex_s + sp0)  - full_l);
    Bv.y = (float)((ex_s + sp0) + (full_l - (ex_l + lp1))) + o4.y;
    A.z  = b4.z + (float)((ex_l + lp1) - (ex_s + sp1)  - full_l);
    Bv.z = (float)((ex_s + sp1) + (full_l - (ex_l + lp2))) + o4.z;
    A.w  = b4.w + (float)((ex_l + lp2) - (ex_s + sp2)  - full_l);
    Bv.w = (float)((ex_s + sp2) + (full_l - (ex_l + lp3))) + o4.w;

    *(float4*)(g_A + idx0) = A;
    *(float4*)(g_B + idx0) = Bv;
}

// ---------------- K4: span fill (write-bound) ------------------------------
__global__ void __launch_bounds__(256) span_kernel(float* __restrict__ out)
{
    const int b  = blockIdx.y;
    const int i0 = blockIdx.x * 16;

    __shared__ float sB[BT];
    __shared__ float sA[16];

    for (int j = threadIdx.x; j < BT; j += 256) sB[j] = g_B[b * BT + j];
    if (threadIdx.x < 16) sA[threadIdx.x] = g_A[b * BT + i0 + threadIdx.x];
    __syncthreads();

    const int j = threadIdx.x * 4;
    const float b0 = sB[j], b1 = sB[j + 1], b2 = sB[j + 2], b3 = sB[j + 3];

    float4* op = (float4*)(out + ((size_t)b * BT + i0) * BT) + threadIdx.x;
#pragma unroll
    for (int r = 0; r < 16; r++) {
        const int   i = i0 + r;
        const float a = sA[r];
        float4 v;
        v.x = (j     >= i) ? (a + b0) : NEG_SPAN;
        v.y = (j + 1 >= i) ? (a + b1) : NEG_SPAN;
        v.z = (j + 2 >= i) ? (a + b2) : NEG_SPAN;
        v.w = (j + 3 >= i) ? (a + b3) : NEG_SPAN;
        __stcs(op, v);
        op += BT / 4;
    }
}

// ---------------- launch ---------------------------------------------------
extern "C" void kernel_launch(void* const* d_in, const int* in_sizes, int n_in,
                              void* d_out, int out_size)
{
    const float* x   = (const float*)d_in[0];
    const float* sen = (const float*)d_in[1];
    const int*   msk = (const int*)  d_in[2];
    const float* Wb  = (const float*)d_in[3];
    const float* bb  = (const float*)d_in[4];
    const float* Wi  = (const float*)d_in[5];
    const float* bi  = (const float*)d_in[6];
    const float* Wo  = (const float*)d_in[7];
    const float* bo  = (const float*)d_in[8];
    float* out = (float*)d_out;

    proj_kernel  <<<dim3(3, 8, NCH),   128>>>(x, Wb, Wi, Wo);
    scores_kernel<<<dim3(BS, BT / 64), 256>>>(sen, msk, x, bb, bi, bo);
    scan_kernel  <<<BS,                256>>>();
    span_kernel  <<<dim3(BT / 16, BS), 256>>>(out);
}

// round 14
// speedup vs baseline: 1.8105x; 1.0191x over previous
#include <cuda_runtime.h>
#include <cuda_bf16.h>
#include <cstdint>
#include <math.h>

#define BS   32
#define BT   1024
#define DIM  512
#define NCH  8
#define CHUNK (DIM / NCH)          // 64
#define SPAN_ROWS 8
#define NEG_MASK (-1000000.0f)
#define NEG_SPAN (-1000.0f)

// ---------------- scratch (device globals; no allocation allowed) ----------
__device__ __align__(16) float g_yp[NCH][3][BS][DIM];   // split-K partials
__device__ __align__(16) float g_sb[BS * BT];
__device__ __align__(16) float g_si[BS * BT];
__device__ __align__(16) float g_so[BS * BT];
__device__ __align__(16) float g_lse[BS * BT];
__device__ __align__(16) float g_A[BS * BT];
__device__ __align__(16) float g_B[BS * BT];

// ---------------- K1: split-K projection, float4 W loads -------------------
__global__ void __launch_bounds__(128)
proj_kernel(const float* __restrict__ x,
            const float* __restrict__ Wb,
            const float* __restrict__ Wi,
            const float* __restrict__ Wo)
{
    const int w    = blockIdx.x;
    const int bgrp = blockIdx.y;
    const int ch   = blockIdx.z;
    const float* W = (w == 0) ? Wb : (w == 1) ? Wi : Wo;

    __shared__ float sx[4][CHUNK];
    for (int i = threadIdx.x; i < 4 * CHUNK; i += 128) {
        int k = i >> 6, e = i & (CHUNK - 1);
        sx[k][e] = x[(size_t)(bgrp * 4 + k) * DIM + ch * CHUNK + e];
    }
    __syncthreads();

    const float4* Wp = (const float4*)(W + (size_t)(ch * CHUNK) * DIM) + threadIdx.x;
    float4 a0 = {0,0,0,0}, a1 = {0,0,0,0}, a2 = {0,0,0,0}, a3 = {0,0,0,0};
#pragma unroll 8
    for (int e = 0; e < CHUNK; e++) {
        const float4 wv = Wp[(size_t)e * (DIM / 4)];
        const float x0 = sx[0][e], x1 = sx[1][e], x2 = sx[2][e], x3 = sx[3][e];
        a0.x = fmaf(wv.x, x0, a0.x); a0.y = fmaf(wv.y, x0, a0.y);
        a0.z = fmaf(wv.z, x0, a0.z); a0.w = fmaf(wv.w, x0, a0.w);
        a1.x = fmaf(wv.x, x1, a1.x); a1.y = fmaf(wv.y, x1, a1.y);
        a1.z = fmaf(wv.z, x1, a1.z); a1.w = fmaf(wv.w, x1, a1.w);
        a2.x = fmaf(wv.x, x2, a2.x); a2.y = fmaf(wv.y, x2, a2.y);
        a2.z = fmaf(wv.z, x2, a2.z); a2.w = fmaf(wv.w, x2, a2.w);
        a3.x = fmaf(wv.x, x3, a3.x); a3.y = fmaf(wv.y, x3, a3.y);
        a3.z = fmaf(wv.z, x3, a3.z); a3.w = fmaf(wv.w, x3, a3.w);
    }
    ((float4*)g_yp[ch][w][bgrp * 4 + 0])[threadIdx.x] = a0;
    ((float4*)g_yp[ch][w][bgrp * 4 + 1])[threadIdx.x] = a1;
    ((float4*)g_yp[ch][w][bgrp * 4 + 2])[threadIdx.x] = a2;
    ((float4*)g_yp[ch][w][bgrp * 4 + 3])[threadIdx.x] = a3;
}

// ---------------- K2: fused reduce + scores + mask + logsumexp -------------
__global__ void __launch_bounds__(256)
scores_kernel(const float* __restrict__ sen,
              const int*   __restrict__ mask,
              const float* __restrict__ x,
              const float* __restrict__ bb,
              const float* __restrict__ bi,
              const float* __restrict__ bo)
{
    const int b     = blockIdx.x;
    const int tbase = blockIdx.y * 64;
    const int warp  = threadIdx.x >> 5;
    const int lane  = threadIdx.x & 31;

    __shared__ float s_y[3][DIM];
    __shared__ float s_c[3];

    for (int i = threadIdx.x; i < 3 * DIM; i += 256) {
        int w = i >> 9, d = i & (DIM - 1);
        float s = 0.f;
#pragma unroll
        for (int ch = 0; ch < NCH; ch++) s += g_yp[ch][w][b][d];
        s_y[w][d] = s;
    }
    if (warp < 3) {
        const float* bias = (warp == 0) ? bb : (warp == 1) ? bi : bo;
        float p = 0.f;
#pragma unroll
        for (int k = lane; k < DIM; k += 32)
            p = fmaf(bias[k], x[(size_t)b * DIM + k], p);
#pragma unroll
        for (int off = 16; off; off >>= 1)
            p += __shfl_xor_sync(0xFFFFFFFFu, p, off);
        if (lane == 0) s_c[warp] = p;
    }
    __syncthreads();

    float4 ryb[4], ryi[4], ryo[4];
    {
        const float4* yb4 = (const float4*)s_y[0];
        const float4* yi4 = (const float4*)s_y[1];
        const float4* yo4 = (const float4*)s_y[2];
#pragma unroll
        for (int j = 0; j < 4; j++) {
            ryb[j] = yb4[lane + j * 32];
            ryi[j] = yi4[lane + j * 32];
            ryo[j] = yo4[lane + j * 32];
        }
    }
    const float cb = s_c[0], ci = s_c[1], co = s_c[2];

#pragma unroll
    for (int tt = 0; tt < 8; tt++) {
        const int t = tbase + warp * 8 + tt;
        const float4* v4 = (const float4*)(sen + ((size_t)b * BT + t) * DIM);

        float ab = 0.f, ai = 0.f, ao = 0.f;
#pragma unroll
        for (int j = 0; j < 4; j++) {
            const float4 vv = __ldcs(v4 + lane + j * 32);
            ab = fmaf(vv.x, ryb[j].x, ab); ab = fmaf(vv.y, ryb[j].y, ab);
            ab = fmaf(vv.z, ryb[j].z, ab); ab = fmaf(vv.w, ryb[j].w, ab);
            ai = fmaf(vv.x, ryi[j].x, ai); ai = fmaf(vv.y, ryi[j].y, ai);
            ai = fmaf(vv.z, ryi[j].z, ai); ai = fmaf(vv.w, ryi[j].w, ai);
            ao = fmaf(vv.x, ryo[j].x, ao); ao = fmaf(vv.y, ryo[j].y, ao);
            ao = fmaf(vv.z, ryo[j].z, ao); ao = fmaf(vv.w, ryo[j].w, ao);
        }
#pragma unroll
        for (int off = 16; off; off >>= 1) {
            ab += __shfl_xor_sync(0xFFFFFFFFu, ab, off);
            ai += __shfl_xor_sync(0xFFFFFFFFu, ai, off);
            ao += __shfl_xor_sync(0xFFFFFFFFu, ao, off);
        }
        if (lane == 0) {
            const int   idx = b * BT + t;
            const int   m   = mask[idx];
            const float sb  = m ? (ab + cb) : NEG_MASK;
            const float si  = m ? (ai + ci) : NEG_MASK;
            const float so  = m ? (ao + co) : 0.0f;
            const float mx  = fmaxf(sb, fmaxf(si, so));
            const float lse = logf(expf(sb - mx) + expf(si - mx) + expf(so - mx)) + mx;
            g_sb[idx]  = sb;
            g_si[idx]  = si;
            g_so[idx]  = so;
            g_lse[idx] = lse;
        }
    }
}

// ---------------- K3: per-batch scans -> A, B ------------------------------
__global__ void __launch_bounds__(256) scan_kernel()
{
    const int b    = blockIdx.x;
    const int tid  = threadIdx.x;
    const int lane = tid & 31, wid = tid >> 5;
    const int idx0 = b * BT + tid * 4;

    const float4 l4 = *(const float4*)(g_lse + idx0);
    const float4 s4 = *(const float4*)(g_si  + idx0);

    const double lp0 = (double)l4.x;
    const double lp1 = lp0 + (double)l4.y;
    const double lp2 = lp1 + (double)l4.z;
    const double lp3 = lp2 + (double)l4.w;
    const double sp0 = (double)s4.x;
    const double sp1 = sp0 + (double)s4.y;
    const double sp2 = sp1 + (double)s4.z;
    const double sp3 = sp2 + (double)s4.w;

    double tl = lp3, ts = sp3;
#pragma unroll
    for (int o = 1; o < 32; o <<= 1) {
        double nl = __shfl_up_sync(0xFFFFFFFFu, tl, o);
        double ns = __shfl_up_sync(0xFFFFFFFFu, ts, o);
        if (lane >= o) { tl += nl; ts += ns; }
    }

    __shared__ double swl[8], sws[8];
    if (lane == 31) { swl[wid] = tl; sws[wid] = ts; }
    __syncthreads();

    double base_l = 0.0, base_s = 0.0, full_l = 0.0;
#pragma unroll
    for (int w = 0; w < 8; w++) {
        double a = swl[w], c = sws[w];
        full_l += a;
        if (w < wid) { base_l += a; base_s += c; }
    }

    const double ex_l = base_l + (tl - lp3);
    const double ex_s = base_s + (ts - sp3);

    const float4 b4 = *(const float4*)(g_sb + idx0);
    const float4 o4 = *(const float4*)(g_so + idx0);

    float4 A, Bv;
    A.x  = b4.x + (float)( ex_l         - ex_s          - full_l);
    Bv.x = (float)( ex_s         + (full_l - (ex_l + lp0))) + o4.x;
    A.y  = b4.y + (float)((ex_l + lp0) - (ex_s + sp0)  - full_l);
    Bv.y = (float)((ex_s + sp0) + (full_l - (ex_l + lp1))) + o4.y;
    A.z  = b4.z + (float)((ex_l + lp1) - (ex_s + sp1)  - full_l);
    Bv.z = (float)((ex_s + sp1) + (full_l - (ex_l + lp2))) + o4.z;
    A.w  = b4.w + (float)((ex_l + lp2) - (ex_s + sp2)  - full_l);
    Bv.w = (float)((ex_s + sp2) + (full_l - (ex_l + lp3))) + o4.w;

    *(float4*)(g_A + idx0) = A;
    *(float4*)(g_B + idx0) = Bv;
}

// ---------------- K4: span fill via smem staging + bulk copy ---------------
// grid (BT/8, BS), block 256. Each block builds an 8x1024 f32 tile (32KB) in
// smem (STS.128, 4cyc issue) and pushes it with ONE cp.async.bulk S2G
// (contiguous 32KB in gmem) -> no per-store STG issue cost.
__global__ void __launch_bounds__(256) span_kernel(float* __restrict__ out)
{
    __shared__ __align__(16) float tile[SPAN_ROWS * BT];

    const int b  = blockIdx.y;
    const int i0 = blockIdx.x * SPAN_ROWS;
    const int j  = threadIdx.x * 4;

    const float4 bv = *(const float4*)(g_B + b * BT + j);
    float a[SPAN_ROWS];
#pragma unroll
    for (int r = 0; r < SPAN_ROWS; r++) a[r] = g_A[b * BT + i0 + r];

    float4* tp = (float4*)tile + threadIdx.x;
    if (j >= i0 + SPAN_ROWS - 1) {
#pragma unroll
        for (int r = 0; r < SPAN_ROWS; r++) {
            float4 v = { a[r] + bv.x, a[r] + bv.y, a[r] + bv.z, a[r] + bv.w };
            tp[r * (BT / 4)] = v;
        }
    } else if (j + 3 < i0) {
        const float4 v = { NEG_SPAN, NEG_SPAN, NEG_SPAN, NEG_SPAN };
#pragma unroll
        for (int r = 0; r < SPAN_ROWS; r++) tp[r * (BT / 4)] = v;
    } else {
#pragma unroll
        for (int r = 0; r < SPAN_ROWS; r++) {
            const int i = i0 + r;
            float4 v;
            v.x = (j     >= i) ? (a[r] + bv.x) : NEG_SPAN;
            v.y = (j + 1 >= i) ? (a[r] + bv.y) : NEG_SPAN;
            v.z = (j + 2 >= i) ? (a[r] + bv.z) : NEG_SPAN;
            v.w = (j + 3 >= i) ? (a[r] + bv.w) : NEG_SPAN;
            tp[r * (BT / 4)] = v;
        }
    }
    __syncthreads();

    if (threadIdx.x == 0) {
        unsigned int saddr;
        asm("{ .reg .u64 t; cvta.to.shared.u64 t, %1; cvt.u32.u64 %0, t; }"
            : "=r"(saddr) : "l"((const void*)tile));
        float* gdst = out + ((size_t)b * BT + i0) * BT;
        asm volatile("fence.proxy.async.shared::cta;" ::: "memory");
        asm volatile("cp.async.bulk.global.shared::cta.bulk_group [%0], [%1], %2;"
                     :: "l"(gdst), "r"(saddr), "r"((unsigned int)(SPAN_ROWS * BT * 4))
                     : "memory");
        asm volatile("cp.async.bulk.commit_group;" ::: "memory");
        asm volatile("cp.async.bulk.wait_group 0;" ::: "memory");
    }
}

// ---------------- launch ---------------------------------------------------
extern "C" void kernel_launch(void* const* d_in, const int* in_sizes, int n_in,
                              void* d_out, int out_size)
{
    const float* x   = (const float*)d_in[0];
    const float* sen = (const float*)d_in[1];
    const int*   msk = (const int*)  d_in[2];
    const float* Wb  = (const float*)d_in[3];
    const float* bb  = (const float*)d_in[4];
    const float* Wi  = (const float*)d_in[5];
    const float* bi  = (const float*)d_in[6];
    const float* Wo  = (const float*)d_in[7];
    const float* bo  = (const float*)d_in[8];
    float* out = (float*)d_out;

    proj_kernel  <<<dim3(3, 8, NCH),          128>>>(x, Wb, Wi, Wo);
    scores_kernel<<<dim3(BS, BT / 64),        256>>>(sen, msk, x, bb, bi, bo);
    scan_kernel  <<<BS,                       256>>>();
    span_kernel  <<<dim3(BT / SPAN_ROWS, BS), 256>>>(out);
}

// round 15
// speedup vs baseline: 1.9420x; 1.0726x over previous
#include <cuda_runtime.h>
#include <cuda_bf16.h>
#include <cstdint>
#include <math.h>

#define BS   32
#define BT   1024
#define DIM  512
#define NCH  8
#define CHUNK (DIM / NCH)          // 64
#define NEG_MASK (-1000000.0f)
#define NEG_SPAN (-1000.0f)

// ---------------- scratch (device globals; no allocation allowed) ----------
__device__ __align__(16) float g_yp[NCH][3][BS][DIM];   // split-K partials
__device__ __align__(16) float g_sb[BS * BT];
__device__ __align__(16) float g_si[BS * BT];
__device__ __align__(16) float g_so[BS * BT];
__device__ __align__(16) float g_lse[BS * BT];
__device__ __align__(16) float g_A[BS * BT];
__device__ __align__(16) float g_B[BS * BT];

// ---------------- K1: split-K projection, float4 W loads -------------------
__global__ void __launch_bounds__(128)
proj_kernel(const float* __restrict__ x,
            const float* __restrict__ Wb,
            const float* __restrict__ Wi,
            const float* __restrict__ Wo)
{
    const int w    = blockIdx.x;
    const int bgrp = blockIdx.y;
    const int ch   = blockIdx.z;
    const float* W = (w == 0) ? Wb : (w == 1) ? Wi : Wo;

    __shared__ float sx[4][CHUNK];
    for (int i = threadIdx.x; i < 4 * CHUNK; i += 128) {
        int k = i >> 6, e = i & (CHUNK - 1);
        sx[k][e] = x[(size_t)(bgrp * 4 + k) * DIM + ch * CHUNK + e];
    }
    __syncthreads();

    const float4* Wp = (const float4*)(W + (size_t)(ch * CHUNK) * DIM) + threadIdx.x;
    float4 a0 = {0,0,0,0}, a1 = {0,0,0,0}, a2 = {0,0,0,0}, a3 = {0,0,0,0};
#pragma unroll 8
    for (int e = 0; e < CHUNK; e++) {
        const float4 wv = Wp[(size_t)e * (DIM / 4)];
        const float x0 = sx[0][e], x1 = sx[1][e], x2 = sx[2][e], x3 = sx[3][e];
        a0.x = fmaf(wv.x, x0, a0.x); a0.y = fmaf(wv.y, x0, a0.y);
        a0.z = fmaf(wv.z, x0, a0.z); a0.w = fmaf(wv.w, x0, a0.w);
        a1.x = fmaf(wv.x, x1, a1.x); a1.y = fmaf(wv.y, x1, a1.y);
        a1.z = fmaf(wv.z, x1, a1.z); a1.w = fmaf(wv.w, x1, a1.w);
        a2.x = fmaf(wv.x, x2, a2.x); a2.y = fmaf(wv.y, x2, a2.y);
        a2.z = fmaf(wv.z, x2, a2.z); a2.w = fmaf(wv.w, x2, a2.w);
        a3.x = fmaf(wv.x, x3, a3.x); a3.y = fmaf(wv.y, x3, a3.y);
        a3.z = fmaf(wv.z, x3, a3.z); a3.w = fmaf(wv.w, x3, a3.w);
    }
    ((float4*)g_yp[ch][w][bgrp * 4 + 0])[threadIdx.x] = a0;
    ((float4*)g_yp[ch][w][bgrp * 4 + 1])[threadIdx.x] = a1;
    ((float4*)g_yp[ch][w][bgrp * 4 + 2])[threadIdx.x] = a2;
    ((float4*)g_yp[ch][w][bgrp * 4 + 3])[threadIdx.x] = a3;
}

// ---------------- K2: fused reduce + scores + mask + logsumexp -------------
// grid (BS, 16), block 256 (8 warps x 8 rows). Rows processed in PAIRS to
// double the loads in flight per warp.
__global__ void __launch_bounds__(256)
scores_kernel(const float* __restrict__ sen,
              const int*   __restrict__ mask,
              const float* __restrict__ x,
              const float* __restrict__ bb,
              const float* __restrict__ bi,
              const float* __restrict__ bo)
{
    const int b     = blockIdx.x;
    const int tbase = blockIdx.y * 64;
    const int warp  = threadIdx.x >> 5;
    const int lane  = threadIdx.x & 31;

    __shared__ float s_y[3][DIM];
    __shared__ float s_c[3];

    for (int i = threadIdx.x; i < 3 * DIM; i += 256) {
        int w = i >> 9, d = i & (DIM - 1);
        float s = 0.f;
#pragma unroll
        for (int ch = 0; ch < NCH; ch++) s += g_yp[ch][w][b][d];
        s_y[w][d] = s;
    }
    if (warp < 3) {
        const float* bias = (warp == 0) ? bb : (warp == 1) ? bi : bo;
        float p = 0.f;
#pragma unroll
        for (int k = lane; k < DIM; k += 32)
            p = fmaf(bias[k], x[(size_t)b * DIM + k], p);
#pragma unroll
        for (int off = 16; off; off >>= 1)
            p += __shfl_xor_sync(0xFFFFFFFFu, p, off);
        if (lane == 0) s_c[warp] = p;
    }
    __syncthreads();

    float4 ryb[4], ryi[4], ryo[4];
    {
        const float4* yb4 = (const float4*)s_y[0];
        const float4* yi4 = (const float4*)s_y[1];
        const float4* yo4 = (const float4*)s_y[2];
#pragma unroll
        for (int j = 0; j < 4; j++) {
            ryb[j] = yb4[lane + j * 32];
            ryi[j] = yi4[lane + j * 32];
            ryo[j] = yo4[lane + j * 32];
        }
    }
    const float cb = s_c[0], ci = s_c[1], co = s_c[2];

#pragma unroll
    for (int p = 0; p < 4; p++) {
        const int t0 = tbase + warp * 8 + p * 2;
        const int t1 = t0 + 1;
        const float4* u4 = (const float4*)(sen + ((size_t)b * BT + t0) * DIM);
        const float4* w4 = (const float4*)(sen + ((size_t)b * BT + t1) * DIM);

        float ab0 = 0.f, ai0 = 0.f, ao0 = 0.f;
        float ab1 = 0.f, ai1 = 0.f, ao1 = 0.f;
#pragma unroll
        for (int j = 0; j < 4; j++) {
            const float4 v0 = __ldcs(u4 + lane + j * 32);
            const float4 v1 = __ldcs(w4 + lane + j * 32);
            ab0 = fmaf(v0.x, ryb[j].x, ab0); ab0 = fmaf(v0.y, ryb[j].y, ab0);
            ab0 = fmaf(v0.z, ryb[j].z, ab0); ab0 = fmaf(v0.w, ryb[j].w, ab0);
            ai0 = fmaf(v0.x, ryi[j].x, ai0); ai0 = fmaf(v0.y, ryi[j].y, ai0);
            ai0 = fmaf(v0.z, ryi[j].z, ai0); ai0 = fmaf(v0.w, ryi[j].w, ai0);
            ao0 = fmaf(v0.x, ryo[j].x, ao0); ao0 = fmaf(v0.y, ryo[j].y, ao0);
            ao0 = fmaf(v0.z, ryo[j].z, ao0); ao0 = fmaf(v0.w, ryo[j].w, ao0);
            ab1 = fmaf(v1.x, ryb[j].x, ab1); ab1 = fmaf(v1.y, ryb[j].y, ab1);
            ab1 = fmaf(v1.z, ryb[j].z, ab1); ab1 = fmaf(v1.w, ryb[j].w, ab1);
            ai1 = fmaf(v1.x, ryi[j].x, ai1); ai1 = fmaf(v1.y, ryi[j].y, ai1);
            ai1 = fmaf(v1.z, ryi[j].z, ai1); ai1 = fmaf(v1.w, ryi[j].w, ai1);
            ao1 = fmaf(v1.x, ryo[j].x, ao1); ao1 = fmaf(v1.y, ryo[j].y, ao1);
            ao1 = fmaf(v1.z, ryo[j].z, ao1); ao1 = fmaf(v1.w, ryo[j].w, ao1);
        }
#pragma unroll
        for (int off = 16; off; off >>= 1) {
            ab0 += __shfl_xor_sync(0xFFFFFFFFu, ab0, off);
            ai0 += __shfl_xor_sync(0xFFFFFFFFu, ai0, off);
            ao0 += __shfl_xor_sync(0xFFFFFFFFu, ao0, off);
            ab1 += __shfl_xor_sync(0xFFFFFFFFu, ab1, off);
            ai1 += __shfl_xor_sync(0xFFFFFFFFu, ai1, off);
            ao1 += __shfl_xor_sync(0xFFFFFFFFu, ao1, off);
        }
        if (lane == 0) {
#pragma unroll
            for (int q = 0; q < 2; q++) {
                const int   t   = q ? t1 : t0;
                const float ab  = q ? ab1 : ab0;
                const float ai  = q ? ai1 : ai0;
                const float ao  = q ? ao1 : ao0;
                const int   idx = b * BT + t;
                const int   m   = mask[idx];
                const float sb  = m ? (ab + cb) : NEG_MASK;
                const float si  = m ? (ai + ci) : NEG_MASK;
                const float so  = m ? (ao + co) : 0.0f;
                const float mx  = fmaxf(sb, fmaxf(si, so));
                const float lse = logf(expf(sb - mx) + expf(si - mx) + expf(so - mx)) + mx;
                g_sb[idx]  = sb;
                g_si[idx]  = si;
                g_so[idx]  = so;
                g_lse[idx] = lse;
            }
        }
    }
}

// ---------------- K3: per-batch scans -> A, B ------------------------------
__global__ void __launch_bounds__(256) scan_kernel()
{
    const int b    = blockIdx.x;
    const int tid  = threadIdx.x;
    const int lane = tid & 31, wid = tid >> 5;
    const int idx0 = b * BT + tid * 4;

    const float4 l4 = *(const float4*)(g_lse + idx0);
    const float4 s4 = *(const float4*)(g_si  + idx0);

    const double lp0 = (double)l4.x;
    const double lp1 = lp0 + (double)l4.y;
    const double lp2 = lp1 + (double)l4.z;
    const double lp3 = lp2 + (double)l4.w;
    const double sp0 = (double)s4.x;
    const double sp1 = sp0 + (double)s4.y;
    const double sp2 = sp1 + (double)s4.z;
    const double sp3 = sp2 + (double)s4.w;

    double tl = lp3, ts = sp3;
#pragma unroll
    for (int o = 1; o < 32; o <<= 1) {
        double nl = __shfl_up_sync(0xFFFFFFFFu, tl, o);
        double ns = __shfl_up_sync(0xFFFFFFFFu, ts, o);
        if (lane >= o) { tl += nl; ts += ns; }
    }

    __shared__ double swl[8], sws[8];
    if (lane == 31) { swl[wid] = tl; sws[wid] = ts; }
    __syncthreads();

    double base_l = 0.0, base_s = 0.0, full_l = 0.0;
#pragma unroll
    for (int w = 0; w < 8; w++) {
        double a = swl[w], c = sws[w];
        full_l += a;
        if (w < wid) { base_l += a; base_s += c; }
    }

    const double ex_l = base_l + (tl - lp3);
    const double ex_s = base_s + (ts - sp3);

    const float4 b4 = *(const float4*)(g_sb + idx0);
    const float4 o4 = *(const float4*)(g_so + idx0);

    float4 A, Bv;
    A.x  = b4.x + (float)( ex_l         - ex_s          - full_l);
    Bv.x = (float)( ex_s         + (full_l - (ex_l + lp0))) + o4.x;
    A.y  = b4.y + (float)((ex_l + lp0) - (ex_s + sp0)  - full_l);
    Bv.y = (float)((ex_s + sp0) + (full_l - (ex_l + lp1))) + o4.y;
    A.z  = b4.z + (float)((ex_l + lp1) - (ex_s + sp1)  - full_l);
    Bv.z = (float)((ex_s + sp1) + (full_l - (ex_l + lp2))) + o4.z;
    A.w  = b4.w + (float)((ex_l + lp2) - (ex_s + sp2)  - full_l);
    Bv.w = (float)((ex_s + sp2) + (full_l - (ex_l + lp3))) + o4.w;

    *(float4*)(g_A + idx0) = A;
    *(float4*)(g_B + idx0) = Bv;
}

// ---------------- K4a: constant lower-triangle fill (independent) ----------
// Writes every float4 block with j+3 < i. Runs on a FORKED stream, overlapped
// with proj/scores/scan. Disjoint from span_upper by construction.
__global__ void __launch_bounds__(256) fill_kernel(float* __restrict__ out)
{
    const int b  = blockIdx.y;
    const int i0 = blockIdx.x * 16;
    const int j  = threadIdx.x * 4;

    if (j >= i0 + 15) return;                 // no row in this tile has j+3 < i

    const float4 v = { NEG_SPAN, NEG_SPAN, NEG_SPAN, NEG_SPAN };
    float4* op = (float4*)(out + ((size_t)b * BT + i0) * BT) + threadIdx.x;

    if (j + 3 < i0) {                         // all 16 rows lower-full
#pragma unroll
        for (int r = 0; r < 16; r++) {
            __stcs(op, v);
            op += BT / 4;
        }
    } else {                                  // straddle: rows i > j+3
        const int r0 = j + 4 - i0;            // first row with i0+r > j+3
        op += r0 * (BT / 4);
        for (int r = r0; r < 16; r++) {
            __stcs(op, v);
            op += BT / 4;
        }
    }
}

// ---------------- K4b: upper-triangle span fill ----------------------------
// Writes every float4 block with j+3 >= i. No smem, no syncthreads, early
// exit for fully-lower threads.
__global__ void __launch_bounds__(256) span_kernel(float* __restrict__ out)
{
    const int b  = blockIdx.y;
    const int i0 = blockIdx.x * 16;
    const int j  = threadIdx.x * 4;

    if (j + 3 < i0) return;                   // fill_kernel covers all rows

    const float4 bv = *(const float4*)(g_B + b * BT + j);
    const float* Ap = g_A + b * BT + i0;
    float4* op = (float4*)(out + ((size_t)b * BT + i0) * BT) + threadIdx.x;

    if (j >= i0 + 15) {                       // all 16 rows fully upper
#pragma unroll
        for (int r = 0; r < 16; r++) {
            const float a = Ap[r];
            float4 v = { a + bv.x, a + bv.y, a + bv.z, a + bv.w };
            __stcs(op, v);
            op += BT / 4;
        }
    } else {                                  // straddle rows
#pragma unroll
        for (int r = 0; r < 16; r++) {
            const int i = i0 + r;
            if (j + 3 >= i) {
                const float a = Ap[r];
                float4 v;
                v.x = (j     >= i) ? (a + bv.x) : NEG_SPAN;
                v.y = (j + 1 >= i) ? (a + bv.y) : NEG_SPAN;
                v.z = (j + 2 >= i) ? (a + bv.z) : NEG_SPAN;
                v.w = (j + 3 >= i) ? (a + bv.w) : NEG_SPAN;
                __stcs(op, v);
            }
            op += BT / 4;
        }
    }
}

// ---------------- launch: fork-join graph ----------------------------------
extern "C" void kernel_launch(void* const* d_in, const int* in_sizes, int n_in,
                              void* d_out, int out_size)
{
    const float* x   = (const float*)d_in[0];
    const float* sen = (const float*)d_in[1];
    const int*   msk = (const int*)  d_in[2];
    const float* Wb  = (const float*)d_in[3];
    const float* bb  = (const float*)d_in[4];
    const float* Wi  = (const float*)d_in[5];
    const float* bi  = (const float*)d_in[6];
    const float* Wo  = (const float*)d_in[7];
    const float* bo  = (const float*)d_in[8];
    float* out = (float*)d_out;

    cudaStream_t s2;
    cudaStreamCreateWithFlags(&s2, cudaStreamNonBlocking);
    cudaEvent_t eFork, eJoin;
    cudaEventCreateWithFlags(&eFork, cudaEventDisableTiming);
    cudaEventCreateWithFlags(&eJoin, cudaEventDisableTiming);

    // fork: constant lower-triangle fill runs concurrently with everything
    cudaEventRecord(eFork, 0);
    cudaStreamWaitEvent(s2, eFork, 0);
    fill_kernel<<<dim3(BT / 16, BS), 256, 0, s2>>>(out);
    cudaEventRecord(eJoin, s2);

    // main chain
    proj_kernel  <<<dim3(3, 8, NCH),   128>>>(x, Wb, Wi, Wo);
    scores_kernel<<<dim3(BS, BT / 64), 256>>>(sen, msk, x, bb, bi, bo);
    scan_kernel  <<<BS,                256>>>();
    span_kernel  <<<dim3(BT / 16, BS), 256>>>(out);

    // join
    cudaStreamWaitEvent(0, eJoin, 0);

    cudaEventDestroy(eFork);
    cudaEventDestroy(eJoin);
    cudaStreamDestroy(s2);
}

// round 17
// speedup vs baseline: 2.0734x; 1.0677x over previous
#include <cuda_runtime.h>
#include <cuda_bf16.h>
#include <cstdint>
#include <math.h>

#define BS   32
#define BT   1024
#define DIM  512
#define NCH  8
#define CHUNK (DIM / NCH)          // 64
#define NEG_MASK (-1000000.0f)
#define NEG_SPAN (-1000.0f)

// ---------------- scratch (device globals; no allocation allowed) ----------
__device__ __align__(16) float g_yp[NCH][3][BS][DIM];   // split-K partials
__device__ __align__(16) float g_sb[BS * BT];
__device__ __align__(16) float g_si[BS * BT];
__device__ __align__(16) float g_so[BS * BT];
__device__ __align__(16) float g_lse[BS * BT];
__device__ __align__(16) float g_A[BS * BT];
__device__ __align__(16) float g_B[BS * BT];

// ---------------- double-float (compensated) arithmetic --------------------
struct df { float h, l; };

__device__ __forceinline__ df df_make(float x) { df r; r.h = x; r.l = 0.f; return r; }

__device__ __forceinline__ df df_add(df a, df b) {
    // Knuth TwoSum on the high parts, fold in the lows, renormalize.
    float s = a.h + b.h;
    float v = s - a.h;
    float e = (a.h - (s - v)) + (b.h - v);
    e += a.l + b.l;
    df r;
    r.h = s + e;
    r.l = e - (r.h - s);
    return r;
}

__device__ __forceinline__ df df_sub(df a, df b) {
    df nb; nb.h = -b.h; nb.l = -b.l;
    return df_add(a, nb);
}

__device__ __forceinline__ df df_shfl_up(df a, int delta) {
    df r;
    r.h = __shfl_up_sync(0xFFFFFFFFu, a.h, delta);
    r.l = __shfl_up_sync(0xFFFFFFFFu, a.l, delta);
    return r;
}

// ---------------- K1: split-K projection, float4 W loads -------------------
__global__ void __launch_bounds__(128)
proj_kernel(const float* __restrict__ x,
            const float* __restrict__ Wb,
            const float* __restrict__ Wi,
            const float* __restrict__ Wo)
{
    const int w    = blockIdx.x;
    const int bgrp = blockIdx.y;
    const int ch   = blockIdx.z;
    const float* W = (w == 0) ? Wb : (w == 1) ? Wi : Wo;

    __shared__ float sx[4][CHUNK];
    for (int i = threadIdx.x; i < 4 * CHUNK; i += 128) {
        int k = i >> 6, e = i & (CHUNK - 1);
        sx[k][e] = x[(size_t)(bgrp * 4 + k) * DIM + ch * CHUNK + e];
    }
    __syncthreads();

    const float4* Wp = (const float4*)(W + (size_t)(ch * CHUNK) * DIM) + threadIdx.x;
    float4 a0 = {0,0,0,0}, a1 = {0,0,0,0}, a2 = {0,0,0,0}, a3 = {0,0,0,0};
#pragma unroll 8
    for (int e = 0; e < CHUNK; e++) {
        const float4 wv = Wp[(size_t)e * (DIM / 4)];
        const float x0 = sx[0][e], x1 = sx[1][e], x2 = sx[2][e], x3 = sx[3][e];
        a0.x = fmaf(wv.x, x0, a0.x); a0.y = fmaf(wv.y, x0, a0.y);
        a0.z = fmaf(wv.z, x0, a0.z); a0.w = fmaf(wv.w, x0, a0.w);
        a1.x = fmaf(wv.x, x1, a1.x); a1.y = fmaf(wv.y, x1, a1.y);
        a1.z = fmaf(wv.z, x1, a1.z); a1.w = fmaf(wv.w, x1, a1.w);
        a2.x = fmaf(wv.x, x2, a2.x); a2.y = fmaf(wv.y, x2, a2.y);
        a2.z = fmaf(wv.z, x2, a2.z); a2.w = fmaf(wv.w, x2, a2.w);
        a3.x = fmaf(wv.x, x3, a3.x); a3.y = fmaf(wv.y, x3, a3.y);
        a3.z = fmaf(wv.z, x3, a3.z); a3.w = fmaf(wv.w, x3, a3.w);
    }
    ((float4*)g_yp[ch][w][bgrp * 4 + 0])[threadIdx.x] = a0;
    ((float4*)g_yp[ch][w][bgrp * 4 + 1])[threadIdx.x] = a1;
    ((float4*)g_yp[ch][w][bgrp * 4 + 2])[threadIdx.x] = a2;
    ((float4*)g_yp[ch][w][bgrp * 4 + 3])[threadIdx.x] = a3;
}

// ---------------- K2: fused reduce + scores + mask + logsumexp -------------
__global__ void __launch_bounds__(256)
scores_kernel(const float* __restrict__ sen,
              const int*   __restrict__ mask,
              const float* __restrict__ x,
              const float* __restrict__ bb,
              const float* __restrict__ bi,
              const float* __restrict__ bo)
{
    const int b     = blockIdx.x;
    const int tbase = blockIdx.y * 64;
    const int warp  = threadIdx.x >> 5;
    const int lane  = threadIdx.x & 31;

    __shared__ float s_y[3][DIM];
    __shared__ float s_c[3];

    for (int i = threadIdx.x; i < 3 * DIM; i += 256) {
        int w = i >> 9, d = i & (DIM - 1);
        float s = 0.f;
#pragma unroll
        for (int ch = 0; ch < NCH; ch++) s += g_yp[ch][w][b][d];
        s_y[w][d] = s;
    }
    if (warp < 3) {
        const float* bias = (warp == 0) ? bb : (warp == 1) ? bi : bo;
        float p = 0.f;
#pragma unroll
        for (int k = lane; k < DIM; k += 32)
            p = fmaf(bias[k], x[(size_t)b * DIM + k], p);
#pragma unroll
        for (int off = 16; off; off >>= 1)
            p += __shfl_xor_sync(0xFFFFFFFFu, p, off);
        if (lane == 0) s_c[warp] = p;
    }
    __syncthreads();

    float4 ryb[4], ryi[4], ryo[4];
    {
        const float4* yb4 = (const float4*)s_y[0];
        const float4* yi4 = (const float4*)s_y[1];
        const float4* yo4 = (const float4*)s_y[2];
#pragma unroll
        for (int j = 0; j < 4; j++) {
            ryb[j] = yb4[lane + j * 32];
            ryi[j] = yi4[lane + j * 32];
            ryo[j] = yo4[lane + j * 32];
        }
    }
    const float cb = s_c[0], ci = s_c[1], co = s_c[2];

#pragma unroll
    for (int p = 0; p < 4; p++) {
        const int t0 = tbase + warp * 8 + p * 2;
        const int t1 = t0 + 1;
        const float4* u4 = (const float4*)(sen + ((size_t)b * BT + t0) * DIM);
        const float4* w4 = (const float4*)(sen + ((size_t)b * BT + t1) * DIM);

        float ab0 = 0.f, ai0 = 0.f, ao0 = 0.f;
        float ab1 = 0.f, ai1 = 0.f, ao1 = 0.f;
#pragma unroll
        for (int j = 0; j < 4; j++) {
            const float4 v0 = __ldcs(u4 + lane + j * 32);
            const float4 v1 = __ldcs(w4 + lane + j * 32);
            ab0 = fmaf(v0.x, ryb[j].x, ab0); ab0 = fmaf(v0.y, ryb[j].y, ab0);
            ab0 = fmaf(v0.z, ryb[j].z, ab0); ab0 = fmaf(v0.w, ryb[j].w, ab0);
            ai0 = fmaf(v0.x, ryi[j].x, ai0); ai0 = fmaf(v0.y, ryi[j].y, ai0);
            ai0 = fmaf(v0.z, ryi[j].z, ai0); ai0 = fmaf(v0.w, ryi[j].w, ai0);
            ao0 = fmaf(v0.x, ryo[j].x, ao0); ao0 = fmaf(v0.y, ryo[j].y, ao0);
            ao0 = fmaf(v0.z, ryo[j].z, ao0); ao0 = fmaf(v0.w, ryo[j].w, ao0);
            ab1 = fmaf(v1.x, ryb[j].x, ab1); ab1 = fmaf(v1.y, ryb[j].y, ab1);
            ab1 = fmaf(v1.z, ryb[j].z, ab1); ab1 = fmaf(v1.w, ryb[j].w, ab1);
            ai1 = fmaf(v1.x, ryi[j].x, ai1); ai1 = fmaf(v1.y, ryi[j].y, ai1);
            ai1 = fmaf(v1.z, ryi[j].z, ai1); ai1 = fmaf(v1.w, ryi[j].w, ai1);
            ao1 = fmaf(v1.x, ryo[j].x, ao1); ao1 = fmaf(v1.y, ryo[j].y, ao1);
            ao1 = fmaf(v1.z, ryo[j].z, ao1); ao1 = fmaf(v1.w, ryo[j].w, ao1);
        }
#pragma unroll
        for (int off = 16; off; off >>= 1) {
            ab0 += __shfl_xor_sync(0xFFFFFFFFu, ab0, off);
            ai0 += __shfl_xor_sync(0xFFFFFFFFu, ai0, off);
            ao0 += __shfl_xor_sync(0xFFFFFFFFu, ao0, off);
            ab1 += __shfl_xor_sync(0xFFFFFFFFu, ab1, off);
            ai1 += __shfl_xor_sync(0xFFFFFFFFu, ai1, off);
            ao1 += __shfl_xor_sync(0xFFFFFFFFu, ao1, off);
        }
        if (lane == 0) {
#pragma unroll
            for (int q = 0; q < 2; q++) {
                const int   t   = q ? t1 : t0;
                const float ab  = q ? ab1 : ab0;
                const float ai  = q ? ai1 : ai0;
                const float ao  = q ? ao1 : ao0;
                const int   idx = b * BT + t;
                const int   m   = mask[idx];
                const float sb  = m ? (ab + cb) : NEG_MASK;
                const float si  = m ? (ai + ci) : NEG_MASK;
                const float so  = m ? (ao + co) : 0.0f;
                const float mx  = fmaxf(sb, fmaxf(si, so));
                const float lse = logf(expf(sb - mx) + expf(si - mx) + expf(so - mx)) + mx;
                g_sb[idx]  = sb;
                g_si[idx]  = si;
                g_so[idx]  = so;
                g_lse[idx] = lse;
            }
        }
    }
}

// ---------------- K3: per-batch scans -> A, B (double-float) ---------------
// grid BS, block 256, thread owns 4 elements. All accumulation in compensated
// float2 (TwoSum) on the FMA pipe -- no FP64.
__global__ void __launch_bounds__(256) scan_kernel()
{
    const int b    = blockIdx.x;
    const int tid  = threadIdx.x;
    const int lane = tid & 31, wid = tid >> 5;
    const int idx0 = b * BT + tid * 4;

    const float4 l4 = *(const float4*)(g_lse + idx0);
    const float4 s4 = *(const float4*)(g_si  + idx0);

    // inclusive prefix inside the 4-chunk
    const df lp0 = df_make(l4.x);
    const df lp1 = df_add(lp0, df_make(l4.y));
    const df lp2 = df_add(lp1, df_make(l4.z));
    const df lp3 = df_add(lp2, df_make(l4.w));
    const df sp0 = df_make(s4.x);
    const df sp1 = df_add(sp0, df_make(s4.y));
    const df sp2 = df_add(sp1, df_make(s4.z));
    const df sp3 = df_add(sp2, df_make(s4.w));

    // inclusive warp scan of chunk totals
    df tl = lp3, ts = sp3;
#pragma unroll
    for (int o = 1; o < 32; o <<= 1) {
        df nl = df_shfl_up(tl, o);
        df ns = df_shfl_up(ts, o);
        if (lane >= o) { tl = df_add(tl, nl); ts = df_add(ts, ns); }
    }

    __shared__ df swl[8], sws[8];
    if (lane == 31) { swl[wid] = tl; sws[wid] = ts; }
    __syncthreads();

    df base_l = df_make(0.f), base_s = df_make(0.f), full_l = df_make(0.f);
#pragma unroll
    for (int w = 0; w < 8; w++) {
        df a = swl[w], c = sws[w];
        full_l = df_add(full_l, a);
        if (w < wid) { base_l = df_add(base_l, a); base_s = df_add(base_s, c); }
    }

    // exclusive prefix before this thread's chunk
    const df ex_l = df_add(base_l, df_sub(tl, lp3));
    const df ex_s = df_add(base_s, df_sub(ts, sp3));

    const float4 b4 = *(const float4*)(g_sb + idx0);
    const float4 o4 = *(const float4*)(g_so + idx0);

    // incl_l[k] = ex_l + lp[k]; A[k] = sb + (incl_l[k-1] - incl_s[k-1] - full)
    // B[k] = incl_s[k-1] + (full - incl_l[k]) + so
    df il0 = df_add(ex_l, lp0), il1 = df_add(ex_l, lp1);
    df il2 = df_add(ex_l, lp2), il3 = df_add(ex_l, lp3);
    df is0 = df_add(ex_s, sp0), is1 = df_add(ex_s, sp1);
    df is2 = df_add(ex_s, sp2);

    float4 A, Bv;
    A.x  = b4.x + df_sub(df_sub(ex_l, ex_s), full_l).h;
    Bv.x = df_add(ex_s, df_sub(full_l, il0)).h + o4.x;
    A.y  = b4.y + df_sub(df_sub(il0, is0), full_l).h;
    Bv.y = df_add(is0, df_sub(full_l, il1)).h + o4.y;
    A.z  = b4.z + df_sub(df_sub(il1, is1), full_l).h;
    Bv.z = df_add(is1, df_sub(full_l, il2)).h + o4.z;
    A.w  = b4.w + df_sub(df_sub(il2, is2), full_l).h;
    Bv.w = df_add(is2, df_sub(full_l, il3)).h + o4.w;

    *(float4*)(g_A + idx0) = A;
    *(float4*)(g_B + idx0) = Bv;
}

// ---------------- K4a: constant lower-triangle fill (independent) ----------
__global__ void __launch_bounds__(256) fill_kernel(float* __restrict__ out)
{
    const int b  = blockIdx.y;
    const int i0 = blockIdx.x * 16;
    const int j  = threadIdx.x * 4;

    if (j >= i0 + 15) return;

    const float4 v = { NEG_SPAN, NEG_SPAN, NEG_SPAN, NEG_SPAN };
    float4* op = (float4*)(out + ((size_t)b * BT + i0) * BT) + threadIdx.x;

    if (j + 3 < i0) {
#pragma unroll
        for (int r = 0; r < 16; r++) {
            __stcs(op, v);
            op += BT / 4;
        }
    } else {
        const int r0 = j + 4 - i0;
        op += r0 * (BT / 4);
        for (int r = r0; r < 16; r++) {
            __stcs(op, v);
            op += BT / 4;
        }
    }
}

// ---------------- K4b: upper-triangle span fill ----------------------------
__global__ void __launch_bounds__(256) span_kernel(float* __restrict__ out)
{
    const int b  = blockIdx.y;
    const int i0 = blockIdx.x * 16;
    const int j  = threadIdx.x * 4;

    if (j + 3 < i0) return;

    const float4 bv = *(const float4*)(g_B + b * BT + j);
    const float* Ap = g_A + b * BT + i0;
    float4* op = (float4*)(out + ((size_t)b * BT + i0) * BT) + threadIdx.x;

    if (j >= i0 + 15) {
#pragma unroll
        for (int r = 0; r < 16; r++) {
            const float a = Ap[r];
            float4 v = { a + bv.x, a + bv.y, a + bv.z, a + bv.w };
            __stcs(op, v);
            op += BT / 4;
        }
    } else {
#pragma unroll
        for (int r = 0; r < 16; r++) {
            const int i = i0 + r;
            if (j + 3 >= i) {
                const float a = Ap[r];
                float4 v;
                v.x = (j     >= i) ? (a + bv.x) : NEG_SPAN;
                v.y = (j + 1 >= i) ? (a + bv.y) : NEG_SPAN;
                v.z = (j + 2 >= i) ? (a + bv.z) : NEG_SPAN;
                v.w = (j + 3 >= i) ? (a + bv.w) : NEG_SPAN;
                __stcs(op, v);
            }
            op += BT / 4;
        }
    }
}

// ---------------- launch: fork-join graph ----------------------------------
extern "C" void kernel_launch(void* const* d_in, const int* in_sizes, int n_in,
                              void* d_out, int out_size)
{
    const float* x   = (const float*)d_in[0];
    const float* sen = (const float*)d_in[1];
    const int*   msk = (const int*)  d_in[2];
    const float* Wb  = (const float*)d_in[3];
    const float* bb  = (const float*)d_in[4];
    const float* Wi  = (const float*)d_in[5];
    const float* bi  = (const float*)d_in[6];
    const float* Wo  = (const float*)d_in[7];
    const float* bo  = (const float*)d_in[8];
    float* out = (float*)d_out;

    cudaStream_t s2;
    cudaStreamCreateWithFlags(&s2, cudaStreamNonBlocking);
    cudaEvent_t eFork, eJoin;
    cudaEventCreateWithFlags(&eFork, cudaEventDisableTiming);
    cudaEventCreateWithFlags(&eJoin, cudaEventDisableTiming);

    // fork: constant lower-triangle fill runs concurrently with everything
    cudaEventRecord(eFork, 0);
    cudaStreamWaitEvent(s2, eFork, 0);
    fill_kernel<<<dim3(BT / 16, BS), 256, 0, s2>>>(out);
    cudaEventRecord(eJoin, s2);

    // main chain
    proj_kernel  <<<dim3(3, 8, NCH),   128>>>(x, Wb, Wi, Wo);
    scores_kernel<<<dim3(BS, BT / 64), 256>>>(sen, msk, x, bb, bi, bo);
    scan_kernel  <<<BS,                256>>>();
    span_kernel  <<<dim3(BT / 16, BS), 256>>>(out);

    // join
    cudaStreamWaitEvent(0, eJoin, 0);

    cudaEventDestroy(eFork);
    cudaEventDestroy(eJoin);
    cudaStreamDestroy(s2);
}